// round 8
// baseline (speedup 1.0000x reference)
#include <cuda_runtime.h>
#include <cstddef>

#define K_DIM 2048
#define M_DIM 512
#define N_DIM 64
#define EPS_F 1e-8f

#define N_CHUNK 4
#define ROWS_PER_CHUNK (K_DIM / N_CHUNK)              // 512
#define TKC 4                                          // rows per gemm block
#define GEMM_BLOCKS_PER_CHUNK (ROWS_PER_CHUNK / TKC)   // 128
#define HARD_BLOCKS 4

// ---------------------------------------------------------------------------
// hard: exact multiset 8th-largest of each w_b column -> scores_hard.
// 4 blocks x 512 thr, warp per column.
// ---------------------------------------------------------------------------
__global__ __launch_bounds__(512)
void hard_kernel(const float* __restrict__ w_b, float* __restrict__ hard) {
    const int lane = threadIdx.x & 31;
    const int wid  = threadIdx.x >> 5;
    const int n    = blockIdx.x * 16 + wid;  // 0..63

    float v[16];
#pragma unroll
    for (int jj = 0; jj < 16; jj++)
        v[jj] = w_b[(lane + 32 * jj) * N_DIM + n];

    float t[8];
#pragma unroll
    for (int i = 0; i < 8; i++) t[i] = -3.402823466e38f;
#pragma unroll
    for (int jj = 0; jj < 16; jj++) {
        float val = v[jj];
        if (val > t[7]) {
            t[7] = val;
#pragma unroll
            for (int i = 7; i > 0; i--) {
                if (t[i] > t[i - 1]) {
                    float tmp = t[i - 1]; t[i - 1] = t[i]; t[i] = tmp;
                }
            }
        }
    }

    float thr = 0.0f;
#pragma unroll
    for (int it = 0; it < 8; it++) {
        float m = t[0];
#pragma unroll
        for (int o = 16; o; o >>= 1)
            m = fmaxf(m, __shfl_xor_sync(0xffffffffu, m, o));
        unsigned bal = __ballot_sync(0xffffffffu, t[0] == m);
        int src = __ffs(bal) - 1;
        if (lane == src) {
#pragma unroll
            for (int i = 0; i < 7; i++) t[i] = t[i + 1];
            t[7] = -3.402823466e38f;
        }
        thr = m;
    }

#pragma unroll
    for (int jj = 0; jj < 16; jj++) {
        float shv = v[jj] - thr + EPS_F;
        shv = fminf(fmaxf(shv, -1.0f), 1.0f);
        hard[(lane + 32 * jj) * N_DIM + n] = (shv + 1.0f) * 0.5f;
    }
}

// ---------------------------------------------------------------------------
// gemm chunk: TKC=4 rows/block, 128 blocks/chunk (fills the machine).
// FFMA2 packed accumulate + 2-deep w_att prefetch; warp-parallel softmax.
// ---------------------------------------------------------------------------
__global__ __launch_bounds__(512, 2)
void gemm_chunk_kernel(const float* __restrict__ x,
                       const float* __restrict__ w_att,
                       float* __restrict__ soft_out,
                       int kbase) {
    __shared__ __align__(16) float sh[TKC * M_DIM];  // 8 KB

    const int tid  = threadIdx.x;
    const int lane = tid & 31;
    const int wid  = tid >> 5;
    const int k0   = kbase + blockIdx.x * TKC;

    // load 4 x-rows: exactly 512 float4
    ((float4*)sh)[tid] = ((const float4*)(x + (size_t)k0 * M_DIM))[tid];
    __syncthreads();

    unsigned long long acc2[TKC];
#pragma unroll
    for (int r = 0; r < TKC; r++) acc2[r] = 0ULL;

    const int j = tid;
    const float* wcol = w_att + j;

    float c0 = wcol[(size_t)0 * M_DIM], c1 = wcol[(size_t)1 * M_DIM];
    float c2 = wcol[(size_t)2 * M_DIM], c3 = wcol[(size_t)3 * M_DIM];
    float n0 = wcol[(size_t)4 * M_DIM], n1 = wcol[(size_t)5 * M_DIM];
    float n2 = wcol[(size_t)6 * M_DIM], n3 = wcol[(size_t)7 * M_DIM];

#pragma unroll 1
    for (int i = 0; i < M_DIM; i += 4) {
        const float* wn = wcol + (size_t)((i + 8) & (M_DIM - 1)) * M_DIM;
        float p0 = wn[(size_t)0 * M_DIM];
        float p1 = wn[(size_t)1 * M_DIM];
        float p2 = wn[(size_t)2 * M_DIM];
        float p3 = wn[(size_t)3 * M_DIM];

        unsigned long long wp0, wp1;
        asm("mov.b64 %0, {%1, %2};" : "=l"(wp0) : "f"(c0), "f"(c1));
        asm("mov.b64 %0, {%1, %2};" : "=l"(wp1) : "f"(c2), "f"(c3));
#pragma unroll
        for (int r = 0; r < TKC; r++) {
            ulonglong2 xp = *(const ulonglong2*)&sh[r * M_DIM + i];
            asm("fma.rn.f32x2 %0, %1, %2, %0;" : "+l"(acc2[r]) : "l"(xp.x), "l"(wp0));
            asm("fma.rn.f32x2 %0, %1, %2, %0;" : "+l"(acc2[r]) : "l"(xp.y), "l"(wp1));
        }
        c0 = n0; c1 = n1; c2 = n2; c3 = n3;
        n0 = p0; n1 = p1; n2 = p2; n3 = p3;
    }

    float acc[TKC];
#pragma unroll
    for (int r = 0; r < TKC; r++) {
        float lo, hi;
        asm("mov.b64 {%0, %1}, %2;" : "=f"(lo), "=f"(hi) : "l"(acc2[r]));
        acc[r] = lo + hi;
    }

    // transpose into shared, then warp w reduces row w (w < 4)
    __syncthreads();
#pragma unroll
    for (int r = 0; r < TKC; r++) sh[r * M_DIM + j] = acc[r];
    __syncthreads();

    if (wid < TKC) {
        const float* row = sh + wid * M_DIM;
        float v[16];
#pragma unroll
        for (int t = 0; t < 16; t++) v[t] = row[lane + 32 * t];

        float mx = v[0];
#pragma unroll
        for (int t = 1; t < 16; t++) mx = fmaxf(mx, v[t]);
#pragma unroll
        for (int o = 16; o; o >>= 1)
            mx = fmaxf(mx, __shfl_xor_sync(0xffffffffu, mx, o));

        float sum = 0.0f;
#pragma unroll
        for (int t = 0; t < 16; t++) {
            v[t] = __expf(v[t] - mx);
            sum += v[t];
        }
#pragma unroll
        for (int o = 16; o; o >>= 1)
            sum += __shfl_xor_sync(0xffffffffu, sum, o);

        float inv = 1.0f / sum;
        float* so = soft_out + (size_t)(k0 + wid) * M_DIM;
#pragma unroll
        for (int t = 0; t < 16; t++)
            so[lane + 32 * t] = v[t] * inv + EPS_F;
    }
}

// ---------------------------------------------------------------------------
// bcast chunk (proven body): mask = hard*soft, out = mask*x. One block per k.
// ---------------------------------------------------------------------------
__global__ __launch_bounds__(512)
void bcast_kernel(const float* __restrict__ x,
                  const float* __restrict__ soft,
                  const float* __restrict__ hard,
                  float* __restrict__ out,
                  float* __restrict__ mask,
                  int kbase) {
    __shared__ float s_sh[M_DIM];
    __shared__ float p_sh[M_DIM];

    const int k = kbase + blockIdx.x;
    {
        int m = threadIdx.x;
        float s  = soft[(size_t)k * M_DIM + m];
        float xv = x[(size_t)k * M_DIM + m];
        s_sh[m] = s;
        p_sh[m] = s * xv;
    }
    __syncthreads();

    const float4* h4 = (const float4*)hard;
    float4* o4 = (float4*)out  + (size_t)k * (M_DIM * N_DIM / 4);
    float4* m4 = (float4*)mask + (size_t)k * (M_DIM * N_DIM / 4);

#pragma unroll 8
    for (int e = threadIdx.x; e < M_DIM * N_DIM / 4; e += 512) {
        int m = e >> 4;
        float4 h = h4[e];
        float s = s_sh[m];
        float p = p_sh[m];

        float4 mw, o;
        mw.x = h.x * s; mw.y = h.y * s; mw.z = h.z * s; mw.w = h.w * s;
        o.x  = h.x * p; o.y  = h.y * p; o.z  = h.z * p; o.w  = h.w * p;

        __stcs(&m4[e], mw);
        __stcs(&o4[e], o);
    }
}

// ---------------------------------------------------------------------------
// d_out layout (reference return order):
//   out         [K,M,N] : offset 0           (67,108,864)
//   scores_hard [M,N]   : offset 67,108,864  (32,768)
//   scores_soft [K,M]   : offset 67,141,632  (1,048,576)
//   mask_weight [K,M,N] : offset 68,190,208  (67,108,864)
//
// Fork-join inside graph capture:
//   sg (high prio): g0 g1 g2 g3          (each chunk fills the machine)
//   sb            : hard, then bcast_c gated on event e_g[c]
// ---------------------------------------------------------------------------
extern "C" void kernel_launch(void* const* d_in, const int* in_sizes, int n_in,
                              void* d_out, int out_size) {
    const float* x     = (const float*)d_in[0];
    const float* w_att = (const float*)d_in[1];
    const float* w_b   = (const float*)d_in[2];

    float* out  = (float*)d_out;
    float* hard = out + 67108864ULL;
    float* soft = out + 67141632ULL;
    float* mask = out + 68190208ULL;

    static cudaStream_t sg = nullptr, sb = nullptr;
    static cudaEvent_t  e_fork, e_g[N_CHUNK], e_join;
    if (sg == nullptr) {
        int lo, hi;
        cudaDeviceGetStreamPriorityRange(&lo, &hi);
        cudaStreamCreateWithPriority(&sg, cudaStreamNonBlocking, hi);  // gemm: high
        cudaStreamCreateWithPriority(&sb, cudaStreamNonBlocking, lo);  // bcast: low
        cudaEventCreateWithFlags(&e_fork, cudaEventDisableTiming);
        for (int c = 0; c < N_CHUNK; c++)
            cudaEventCreateWithFlags(&e_g[c], cudaEventDisableTiming);
        cudaEventCreateWithFlags(&e_join, cudaEventDisableTiming);
    }

    // fork from the (captured) default stream
    cudaEventRecord(e_fork, 0);
    cudaStreamWaitEvent(sg, e_fork, 0);
    cudaStreamWaitEvent(sb, e_fork, 0);

    // hard runs on sb first (parallel with gemm chunk 0)
    hard_kernel<<<HARD_BLOCKS, 512, 0, sb>>>(w_b, hard);

    for (int c = 0; c < N_CHUNK; c++) {
        gemm_chunk_kernel<<<GEMM_BLOCKS_PER_CHUNK, 512, 0, sg>>>(
            x, w_att, soft, c * ROWS_PER_CHUNK);
        cudaEventRecord(e_g[c], sg);
        cudaStreamWaitEvent(sb, e_g[c], 0);
        bcast_kernel<<<ROWS_PER_CHUNK, 512, 0, sb>>>(
            x, soft, hard, out, mask, c * ROWS_PER_CHUNK);
    }

    // join back to the default stream (bcast3 transitively covers sg)
    cudaEventRecord(e_join, sb);
    cudaStreamWaitEvent(0, e_join, 0);
}

// round 9
// speedup vs baseline: 1.0004x; 1.0004x over previous
#include <cuda_runtime.h>
#include <cstddef>

#define K_DIM 2048
#define M_DIM 512
#define N_DIM 64
#define EPS_F 1e-8f

#define N_CHUNK 4
#define ROWS_PER_CHUNK (K_DIM / N_CHUNK)              // 512
#define TKC 4                                          // rows per gemm block
#define GEMM_BLOCKS_PER_CHUNK (ROWS_PER_CHUNK / TKC)   // 128
#define HARD_BLOCKS 4

// ---------------------------------------------------------------------------
// hard: exact multiset 8th-largest of each w_b column -> scores_hard.
// 4 blocks x 512 thr, warp per column.
// ---------------------------------------------------------------------------
__global__ __launch_bounds__(512)
void hard_kernel(const float* __restrict__ w_b, float* __restrict__ hard) {
    const int lane = threadIdx.x & 31;
    const int wid  = threadIdx.x >> 5;
    const int n    = blockIdx.x * 16 + wid;  // 0..63

    float v[16];
#pragma unroll
    for (int jj = 0; jj < 16; jj++)
        v[jj] = w_b[(lane + 32 * jj) * N_DIM + n];

    float t[8];
#pragma unroll
    for (int i = 0; i < 8; i++) t[i] = -3.402823466e38f;
#pragma unroll
    for (int jj = 0; jj < 16; jj++) {
        float val = v[jj];
        if (val > t[7]) {
            t[7] = val;
#pragma unroll
            for (int i = 7; i > 0; i--) {
                if (t[i] > t[i - 1]) {
                    float tmp = t[i - 1]; t[i - 1] = t[i]; t[i] = tmp;
                }
            }
        }
    }

    float thr = 0.0f;
#pragma unroll
    for (int it = 0; it < 8; it++) {
        float m = t[0];
#pragma unroll
        for (int o = 16; o; o >>= 1)
            m = fmaxf(m, __shfl_xor_sync(0xffffffffu, m, o));
        unsigned bal = __ballot_sync(0xffffffffu, t[0] == m);
        int src = __ffs(bal) - 1;
        if (lane == src) {
#pragma unroll
            for (int i = 0; i < 7; i++) t[i] = t[i + 1];
            t[7] = -3.402823466e38f;
        }
        thr = m;
    }

#pragma unroll
    for (int jj = 0; jj < 16; jj++) {
        float shv = v[jj] - thr + EPS_F;
        shv = fminf(fmaxf(shv, -1.0f), 1.0f);
        hard[(lane + 32 * jj) * N_DIM + n] = (shv + 1.0f) * 0.5f;
    }
}

// ---------------------------------------------------------------------------
// gemm chunk: TKC=4 rows/block, 128 blocks/chunk (fills the machine).
// FFMA2 packed accumulate + 2-deep w_att prefetch; warp-parallel softmax.
// ---------------------------------------------------------------------------
__global__ __launch_bounds__(512, 2)
void gemm_chunk_kernel(const float* __restrict__ x,
                       const float* __restrict__ w_att,
                       float* __restrict__ soft_out,
                       int kbase) {
    __shared__ __align__(16) float sh[TKC * M_DIM];  // 8 KB

    const int tid  = threadIdx.x;
    const int lane = tid & 31;
    const int wid  = tid >> 5;
    const int k0   = kbase + blockIdx.x * TKC;

    // load 4 x-rows: exactly 512 float4
    ((float4*)sh)[tid] = ((const float4*)(x + (size_t)k0 * M_DIM))[tid];
    __syncthreads();

    unsigned long long acc2[TKC];
#pragma unroll
    for (int r = 0; r < TKC; r++) acc2[r] = 0ULL;

    const int j = tid;
    const float* wcol = w_att + j;

    float c0 = wcol[(size_t)0 * M_DIM], c1 = wcol[(size_t)1 * M_DIM];
    float c2 = wcol[(size_t)2 * M_DIM], c3 = wcol[(size_t)3 * M_DIM];
    float n0 = wcol[(size_t)4 * M_DIM], n1 = wcol[(size_t)5 * M_DIM];
    float n2 = wcol[(size_t)6 * M_DIM], n3 = wcol[(size_t)7 * M_DIM];

#pragma unroll 1
    for (int i = 0; i < M_DIM; i += 4) {
        const float* wn = wcol + (size_t)((i + 8) & (M_DIM - 1)) * M_DIM;
        float p0 = wn[(size_t)0 * M_DIM];
        float p1 = wn[(size_t)1 * M_DIM];
        float p2 = wn[(size_t)2 * M_DIM];
        float p3 = wn[(size_t)3 * M_DIM];

        unsigned long long wp0, wp1;
        asm("mov.b64 %0, {%1, %2};" : "=l"(wp0) : "f"(c0), "f"(c1));
        asm("mov.b64 %0, {%1, %2};" : "=l"(wp1) : "f"(c2), "f"(c3));
#pragma unroll
        for (int r = 0; r < TKC; r++) {
            ulonglong2 xp = *(const ulonglong2*)&sh[r * M_DIM + i];
            asm("fma.rn.f32x2 %0, %1, %2, %0;" : "+l"(acc2[r]) : "l"(xp.x), "l"(wp0));
            asm("fma.rn.f32x2 %0, %1, %2, %0;" : "+l"(acc2[r]) : "l"(xp.y), "l"(wp1));
        }
        c0 = n0; c1 = n1; c2 = n2; c3 = n3;
        n0 = p0; n1 = p1; n2 = p2; n3 = p3;
    }

    float acc[TKC];
#pragma unroll
    for (int r = 0; r < TKC; r++) {
        float lo, hi;
        asm("mov.b64 {%0, %1}, %2;" : "=f"(lo), "=f"(hi) : "l"(acc2[r]));
        acc[r] = lo + hi;
    }

    // transpose into shared, then warp w reduces row w (w < 4)
    __syncthreads();
#pragma unroll
    for (int r = 0; r < TKC; r++) sh[r * M_DIM + j] = acc[r];
    __syncthreads();

    if (wid < TKC) {
        const float* row = sh + wid * M_DIM;
        float v[16];
#pragma unroll
        for (int t = 0; t < 16; t++) v[t] = row[lane + 32 * t];

        float mx = v[0];
#pragma unroll
        for (int t = 1; t < 16; t++) mx = fmaxf(mx, v[t]);
#pragma unroll
        for (int o = 16; o; o >>= 1)
            mx = fmaxf(mx, __shfl_xor_sync(0xffffffffu, mx, o));

        float sum = 0.0f;
#pragma unroll
        for (int t = 0; t < 16; t++) {
            v[t] = __expf(v[t] - mx);
            sum += v[t];
        }
#pragma unroll
        for (int o = 16; o; o >>= 1)
            sum += __shfl_xor_sync(0xffffffffu, sum, o);

        float inv = 1.0f / sum;
        float* so = soft_out + (size_t)(k0 + wid) * M_DIM;
#pragma unroll
        for (int t = 0; t < 16; t++)
            so[lane + 32 * t] = v[t] * inv + EPS_F;
    }
}

// ---------------------------------------------------------------------------
// bcast chunk (proven body): mask = hard*soft, out = mask*x. One block per k.
// ---------------------------------------------------------------------------
__global__ __launch_bounds__(512)
void bcast_kernel(const float* __restrict__ x,
                  const float* __restrict__ soft,
                  const float* __restrict__ hard,
                  float* __restrict__ out,
                  float* __restrict__ mask,
                  int kbase) {
    __shared__ float s_sh[M_DIM];
    __shared__ float p_sh[M_DIM];

    const int k = kbase + blockIdx.x;
    {
        int m = threadIdx.x;
        float s  = soft[(size_t)k * M_DIM + m];
        float xv = x[(size_t)k * M_DIM + m];
        s_sh[m] = s;
        p_sh[m] = s * xv;
    }
    __syncthreads();

    const float4* h4 = (const float4*)hard;
    float4* o4 = (float4*)out  + (size_t)k * (M_DIM * N_DIM / 4);
    float4* m4 = (float4*)mask + (size_t)k * (M_DIM * N_DIM / 4);

#pragma unroll 8
    for (int e = threadIdx.x; e < M_DIM * N_DIM / 4; e += 512) {
        int m = e >> 4;
        float4 h = h4[e];
        float s = s_sh[m];
        float p = p_sh[m];

        float4 mw, o;
        mw.x = h.x * s; mw.y = h.y * s; mw.z = h.z * s; mw.w = h.w * s;
        o.x  = h.x * p; o.y  = h.y * p; o.z  = h.z * p; o.w  = h.w * p;

        __stcs(&m4[e], mw);
        __stcs(&o4[e], o);
    }
}

// ---------------------------------------------------------------------------
// d_out layout (reference return order):
//   out         [K,M,N] : offset 0           (67,108,864)
//   scores_hard [M,N]   : offset 67,108,864  (32,768)
//   scores_soft [K,M]   : offset 67,141,632  (1,048,576)
//   mask_weight [K,M,N] : offset 68,190,208  (67,108,864)
//
// Fork-join inside graph capture:
//   sg (high prio): g0 g1 g2 g3          (each chunk fills the machine)
//   sb            : hard, then bcast_c gated on event e_g[c]
// ---------------------------------------------------------------------------
extern "C" void kernel_launch(void* const* d_in, const int* in_sizes, int n_in,
                              void* d_out, int out_size) {
    const float* x     = (const float*)d_in[0];
    const float* w_att = (const float*)d_in[1];
    const float* w_b   = (const float*)d_in[2];

    float* out  = (float*)d_out;
    float* hard = out + 67108864ULL;
    float* soft = out + 67141632ULL;
    float* mask = out + 68190208ULL;

    static cudaStream_t sg = nullptr, sb = nullptr;
    static cudaEvent_t  e_fork, e_g[N_CHUNK], e_join;
    if (sg == nullptr) {
        int lo, hi;
        cudaDeviceGetStreamPriorityRange(&lo, &hi);
        cudaStreamCreateWithPriority(&sg, cudaStreamNonBlocking, hi);  // gemm: high
        cudaStreamCreateWithPriority(&sb, cudaStreamNonBlocking, lo);  // bcast: low
        cudaEventCreateWithFlags(&e_fork, cudaEventDisableTiming);
        for (int c = 0; c < N_CHUNK; c++)
            cudaEventCreateWithFlags(&e_g[c], cudaEventDisableTiming);
        cudaEventCreateWithFlags(&e_join, cudaEventDisableTiming);
    }

    // fork from the (captured) default stream
    cudaEventRecord(e_fork, 0);
    cudaStreamWaitEvent(sg, e_fork, 0);
    cudaStreamWaitEvent(sb, e_fork, 0);

    // hard runs on sb first (parallel with gemm chunk 0)
    hard_kernel<<<HARD_BLOCKS, 512, 0, sb>>>(w_b, hard);

    for (int c = 0; c < N_CHUNK; c++) {
        gemm_chunk_kernel<<<GEMM_BLOCKS_PER_CHUNK, 512, 0, sg>>>(
            x, w_att, soft, c * ROWS_PER_CHUNK);
        cudaEventRecord(e_g[c], sg);
        cudaStreamWaitEvent(sb, e_g[c], 0);
        bcast_kernel<<<ROWS_PER_CHUNK, 512, 0, sb>>>(
            x, soft, hard, out, mask, c * ROWS_PER_CHUNK);
    }

    // join back to the default stream (bcast3 transitively covers sg)
    cudaEventRecord(e_join, sb);
    cudaStreamWaitEvent(0, e_join, 0);
}

// round 14
// speedup vs baseline: 1.4284x; 1.4278x over previous
#include <cuda_runtime.h>
#include <cstddef>

#define K_DIM 2048
#define M_DIM 512
#define N_DIM 64
#define TK    16                    // rows per producer block
#define PR    8                     // rows per pass (2 passes)
#define EPS_F 1e-8f

#define P_BLOCKS 128                // producers (TK=16 each)
#define H_BLOCKS 4                  // hard blocks
#define C_BLOCKS (K_DIM)            // one consumer block per k-row
#define GRID_TOTAL (P_BLOCKS + H_BLOCKS + C_BLOCKS)  // 2180
#define N_FLAGS (P_BLOCKS * 2)      // 256: flag[g]=pass1 of block g, flag[128+g]=pass2

__device__ unsigned g_flag[N_FLAGS];
__device__ unsigned g_hard;

__global__ void reset_kernel() {
    if (threadIdx.x < N_FLAGS) g_flag[threadIdx.x] = 0u;
    if (threadIdx.x == 0) g_hard = 0u;
}

__device__ __forceinline__ unsigned ld_acq(const unsigned* p) {
    unsigned v;
    asm volatile("ld.acquire.gpu.u32 %0, [%1];" : "=r"(v) : "l"(p) : "memory");
    return v;
}

// ---------------------------------------------------------------------------
// Single kernel, roles by bid (single wave of producers guaranteed):
//   bid <  128          : producer — gemm+softmax for 16 rows, 2 passes of 8,
//                         flag after each pass (soft -> global).
//   128 <= bid < 132    : scores_hard (exact multiset 8th-largest), g_hard++.
//   bid >= 132          : consumer — waits for its row's pass flag, then
//                         streams mask/out stores for ONE k-row.
// ---------------------------------------------------------------------------
__global__ __launch_bounds__(512, 2)
void fused_overlap_kernel(const float* __restrict__ x,
                          const float* __restrict__ w_att,
                          const float* __restrict__ w_b,
                          float* __restrict__ out,
                          float* __restrict__ hard,
                          float* __restrict__ soft,
                          float* __restrict__ mask) {
    __shared__ __align__(16) float x_sh[TK * M_DIM];  // 32 KB (consumer: s/p rows)
    __shared__ __align__(16) float a_sh[PR * M_DIM];  // 16 KB (acc transpose)

    const int tid  = threadIdx.x;
    const int lane = tid & 31;
    const int wid  = tid >> 5;
    const int bid  = blockIdx.x;

    if (bid < P_BLOCKS) {
        // ======================= producer =======================
        const int k0 = bid * TK;

        // load 16 x-rows (2048 float4, 4 per thread)
        {
            const float4* xs4 = (const float4*)(x + (size_t)k0 * M_DIM);
            float4* d4 = (float4*)x_sh;
#pragma unroll
            for (int e = 0; e < TK * M_DIM / 4 / 512; e++)
                d4[tid + e * 512] = xs4[tid + e * 512];
        }
        __syncthreads();

        const int j = tid;
        const float* wcol = w_att + j;

#pragma unroll 1
        for (int p = 0; p < 2; p++) {
            const int rb = p * PR;

            unsigned long long acc2[PR];
#pragma unroll
            for (int r = 0; r < PR; r++) acc2[r] = 0ULL;

            // 2-deep w_att prefetch pipeline
            float c0 = wcol[(size_t)0 * M_DIM], c1 = wcol[(size_t)1 * M_DIM];
            float c2 = wcol[(size_t)2 * M_DIM], c3 = wcol[(size_t)3 * M_DIM];
            float n0 = wcol[(size_t)4 * M_DIM], n1 = wcol[(size_t)5 * M_DIM];
            float n2 = wcol[(size_t)6 * M_DIM], n3 = wcol[(size_t)7 * M_DIM];

#pragma unroll 1
            for (int i = 0; i < M_DIM; i += 4) {
                const float* wn = wcol + (size_t)((i + 8) & (M_DIM - 1)) * M_DIM;
                float q0 = wn[(size_t)0 * M_DIM];
                float q1 = wn[(size_t)1 * M_DIM];
                float q2 = wn[(size_t)2 * M_DIM];
                float q3 = wn[(size_t)3 * M_DIM];

                unsigned long long wp0, wp1;
                asm("mov.b64 %0, {%1, %2};" : "=l"(wp0) : "f"(c0), "f"(c1));
                asm("mov.b64 %0, {%1, %2};" : "=l"(wp1) : "f"(c2), "f"(c3));
#pragma unroll
                for (int r = 0; r < PR; r++) {
                    ulonglong2 xp = *(const ulonglong2*)&x_sh[(rb + r) * M_DIM + i];
                    asm("fma.rn.f32x2 %0, %1, %2, %0;" : "+l"(acc2[r]) : "l"(xp.x), "l"(wp0));
                    asm("fma.rn.f32x2 %0, %1, %2, %0;" : "+l"(acc2[r]) : "l"(xp.y), "l"(wp1));
                }
                c0 = n0; c1 = n1; c2 = n2; c3 = n3;
                n0 = q0; n1 = q1; n2 = q2; n3 = q3;
            }

            // transpose accumulators into a_sh, warp w reduces row w (w < 8)
            __syncthreads();   // a_sh safe to overwrite (pass-1 reads done)
#pragma unroll
            for (int r = 0; r < PR; r++) {
                float lo, hi;
                asm("mov.b64 {%0, %1}, %2;" : "=f"(lo), "=f"(hi) : "l"(acc2[r]));
                a_sh[r * M_DIM + j] = lo + hi;
            }
            __syncthreads();

            if (wid < PR) {
                const float* row = a_sh + wid * M_DIM;
                float v[16];
#pragma unroll
                for (int t = 0; t < 16; t++) v[t] = row[lane + 32 * t];

                float mx = v[0];
#pragma unroll
                for (int t = 1; t < 16; t++) mx = fmaxf(mx, v[t]);
#pragma unroll
                for (int o = 16; o; o >>= 1)
                    mx = fmaxf(mx, __shfl_xor_sync(0xffffffffu, mx, o));

                float sum = 0.0f;
#pragma unroll
                for (int t = 0; t < 16; t++) {
                    v[t] = __expf(v[t] - mx);
                    sum += v[t];
                }
#pragma unroll
                for (int o = 16; o; o >>= 1)
                    sum += __shfl_xor_sync(0xffffffffu, sum, o);

                float inv = 1.0f / sum;
                float* so = soft + (size_t)(k0 + rb + wid) * M_DIM;
#pragma unroll
                for (int t = 0; t < 16; t++)
                    so[lane + 32 * t] = v[t] * inv + EPS_F;
            }

            __threadfence();   // make soft stores globally visible
            __syncthreads();
            if (tid == 0)
                atomicExch(&g_flag[p * P_BLOCKS + bid], 1u);
        }
        return;
    }

    if (bid < P_BLOCKS + H_BLOCKS) {
        // ======================= hard =======================
        const int n = (bid - P_BLOCKS) * 16 + wid;  // 0..63

        float v[16];
#pragma unroll
        for (int jj = 0; jj < 16; jj++)
            v[jj] = w_b[(lane + 32 * jj) * N_DIM + n];

        float t[8];
#pragma unroll
        for (int i = 0; i < 8; i++) t[i] = -3.402823466e38f;
#pragma unroll
        for (int jj = 0; jj < 16; jj++) {
            float val = v[jj];
            if (val > t[7]) {
                t[7] = val;
#pragma unroll
                for (int i = 7; i > 0; i--) {
                    if (t[i] > t[i - 1]) {
                        float tmp = t[i - 1]; t[i - 1] = t[i]; t[i] = tmp;
                    }
                }
            }
        }

        float thr = 0.0f;
#pragma unroll
        for (int it = 0; it < 8; it++) {
            float m = t[0];
#pragma unroll
            for (int o = 16; o; o >>= 1)
                m = fmaxf(m, __shfl_xor_sync(0xffffffffu, m, o));
            unsigned bal = __ballot_sync(0xffffffffu, t[0] == m);
            int src = __ffs(bal) - 1;
            if (lane == src) {
#pragma unroll
                for (int i = 0; i < 7; i++) t[i] = t[i + 1];
                t[7] = -3.402823466e38f;
            }
            thr = m;
        }

#pragma unroll
        for (int jj = 0; jj < 16; jj++) {
            float shv = v[jj] - thr + EPS_F;
            shv = fminf(fmaxf(shv, -1.0f), 1.0f);
            hard[(lane + 32 * jj) * N_DIM + n] = (shv + 1.0f) * 0.5f;
        }
        __threadfence();
        __syncthreads();
        if (tid == 0) atomicAdd(&g_hard, 1u);
        return;
    }

    // ======================= consumer =======================
    // cb in [0,2048): first 1024 map to pass-1 rows in block order,
    // next 1024 to pass-2 rows. flag index = cb>>3 in both halves.
    const int cb = bid - (P_BLOCKS + H_BLOCKS);
    const int fidx = cb >> 3;                        // 0..255
    const int pg   = (cb & 1023) >> 3;               // producer block 0..127
    const int pp   = cb >> 10;                       // pass 0/1
    const int k    = pg * TK + pp * PR + (cb & 7);   // global row

    if (tid == 0) {
        while (ld_acq(&g_hard) < (unsigned)H_BLOCKS) __nanosleep(128);
        while (ld_acq(&g_flag[fidx]) == 0u) __nanosleep(128);
    }
    __syncthreads();

    float* s_sh = x_sh;
    float* p_sh = x_sh + M_DIM;
    {
        int m = tid;
        float s  = soft[(size_t)k * M_DIM + m];
        float xv = x[(size_t)k * M_DIM + m];
        s_sh[m] = s;
        p_sh[m] = s * xv;
    }
    __syncthreads();

    const float4* h4 = (const float4*)hard;
    float4* o4 = (float4*)out  + (size_t)k * (M_DIM * N_DIM / 4);
    float4* m4 = (float4*)mask + (size_t)k * (M_DIM * N_DIM / 4);

#pragma unroll 8
    for (int e = tid; e < M_DIM * N_DIM / 4; e += 512) {
        int m = e >> 4;
        float4 h = h4[e];
        float s = s_sh[m];
        float p = p_sh[m];

        float4 mw, o;
        mw.x = h.x * s; mw.y = h.y * s; mw.z = h.z * s; mw.w = h.w * s;
        o.x  = h.x * p; o.y  = h.y * p; o.z  = h.z * p; o.w  = h.w * p;

        __stcs(&m4[e], mw);
        __stcs(&o4[e], o);
    }
}

// ---------------------------------------------------------------------------
// d_out layout (reference return order):
//   out         [K,M,N] : offset 0           (67,108,864)
//   scores_hard [M,N]   : offset 67,108,864  (32,768)
//   scores_soft [K,M]   : offset 67,141,632  (1,048,576)
//   mask_weight [K,M,N] : offset 68,190,208  (67,108,864)
// ---------------------------------------------------------------------------
extern "C" void kernel_launch(void* const* d_in, const int* in_sizes, int n_in,
                              void* d_out, int out_size) {
    const float* x     = (const float*)d_in[0];
    const float* w_att = (const float*)d_in[1];
    const float* w_b   = (const float*)d_in[2];

    float* out  = (float*)d_out;
    float* hard = out + 67108864ULL;
    float* soft = out + 67141632ULL;
    float* mask = out + 68190208ULL;

    reset_kernel<<<1, 256>>>();
    fused_overlap_kernel<<<GRID_TOTAL, 512>>>(x, w_att, w_b, out, hard, soft, mask);
}

// round 17
// speedup vs baseline: 1.4702x; 1.0293x over previous
#include <cuda_runtime.h>
#include <cstddef>

#define K_DIM 2048
#define M_DIM 512
#define N_DIM 64
#define EPS_F 1e-8f

// 148 gemm blocks: 124 x 14 rows + 24 x 13 rows = 2048.
// Blocks 144..147 (13-row) also compute scores_hard first (16 cols each).
#define NB14 124
#define GRID1 148
#define R_MAX 14

// ---------------------------------------------------------------------------
// gemm+softmax for R rows starting at k0 (R compile-time: 13 or 14).
// FFMA2 packed accumulate + 2-deep w_att prefetch; warp-parallel softmax.
// x_sh reused for the accumulator transpose.
// ---------------------------------------------------------------------------
template <int R>
__device__ __forceinline__ void gemm_softmax_rows(
    const float* __restrict__ x, const float* __restrict__ w_att,
    float* __restrict__ soft_out, float* x_sh, int k0,
    int tid, int lane, int wid)
{
    // load R x-rows (R*128 float4)
    {
        const float4* xs4 = (const float4*)(x + (size_t)k0 * M_DIM);
        float4* d4 = (float4*)x_sh;
        for (int e = tid; e < R * (M_DIM / 4); e += 512)
            d4[e] = xs4[e];
    }
    __syncthreads();

    unsigned long long acc2[R];
#pragma unroll
    for (int r = 0; r < R; r++) acc2[r] = 0ULL;

    const int j = tid;
    const float* wcol = w_att + j;

    float c0 = wcol[(size_t)0 * M_DIM], c1 = wcol[(size_t)1 * M_DIM];
    float c2 = wcol[(size_t)2 * M_DIM], c3 = wcol[(size_t)3 * M_DIM];
    float n0 = wcol[(size_t)4 * M_DIM], n1 = wcol[(size_t)5 * M_DIM];
    float n2 = wcol[(size_t)6 * M_DIM], n3 = wcol[(size_t)7 * M_DIM];

#pragma unroll 1
    for (int i = 0; i < M_DIM; i += 4) {
        const float* wn = wcol + (size_t)((i + 8) & (M_DIM - 1)) * M_DIM;
        float q0 = wn[(size_t)0 * M_DIM];
        float q1 = wn[(size_t)1 * M_DIM];
        float q2 = wn[(size_t)2 * M_DIM];
        float q3 = wn[(size_t)3 * M_DIM];

        unsigned long long wp0, wp1;
        asm("mov.b64 %0, {%1, %2};" : "=l"(wp0) : "f"(c0), "f"(c1));
        asm("mov.b64 %0, {%1, %2};" : "=l"(wp1) : "f"(c2), "f"(c3));
#pragma unroll
        for (int r = 0; r < R; r++) {
            ulonglong2 xp = *(const ulonglong2*)&x_sh[r * M_DIM + i];
            asm("fma.rn.f32x2 %0, %1, %2, %0;" : "+l"(acc2[r]) : "l"(xp.x), "l"(wp0));
            asm("fma.rn.f32x2 %0, %1, %2, %0;" : "+l"(acc2[r]) : "l"(xp.y), "l"(wp1));
        }
        c0 = n0; c1 = n1; c2 = n2; c3 = n3;
        n0 = q0; n1 = q1; n2 = q2; n3 = q3;
    }

    // transpose accumulators into x_sh (x no longer needed)
    __syncthreads();
#pragma unroll
    for (int r = 0; r < R; r++) {
        float lo, hi;
        asm("mov.b64 {%0, %1}, %2;" : "=f"(lo), "=f"(hi) : "l"(acc2[r]));
        x_sh[r * M_DIM + j] = lo + hi;
    }
    __syncthreads();

    // warp w reduces row w (w < R)
    if (wid < R) {
        const float* row = x_sh + wid * M_DIM;
        float v[16];
#pragma unroll
        for (int t = 0; t < 16; t++) v[t] = row[lane + 32 * t];

        float mx = v[0];
#pragma unroll
        for (int t = 1; t < 16; t++) mx = fmaxf(mx, v[t]);
#pragma unroll
        for (int o = 16; o; o >>= 1)
            mx = fmaxf(mx, __shfl_xor_sync(0xffffffffu, mx, o));

        float sum = 0.0f;
#pragma unroll
        for (int t = 0; t < 16; t++) {
            v[t] = __expf(v[t] - mx);
            sum += v[t];
        }
#pragma unroll
        for (int o = 16; o; o >>= 1)
            sum += __shfl_xor_sync(0xffffffffu, sum, o);

        float inv = 1.0f / sum;
        float* so = soft_out + (size_t)(k0 + wid) * M_DIM;
#pragma unroll
        for (int t = 0; t < 16; t++)
            so[lane + 32 * t] = v[t] * inv + EPS_F;
    }
}

// ---------------------------------------------------------------------------
// Kernel 1: 148 blocks. b<124: 14 rows @ 14b. b>=124: 13 rows @ 1736+13(b-124).
// Blocks 144..147 additionally compute scores_hard (before gemm; hidden
// under the 14-row blocks' critical path).
// ---------------------------------------------------------------------------
__global__ __launch_bounds__(512, 1)
void gemm_softmax_hard_kernel(const float* __restrict__ x,
                              const float* __restrict__ w_att,
                              const float* __restrict__ w_b,
                              float* __restrict__ soft_out,
                              float* __restrict__ hard_out) {
    __shared__ __align__(16) float x_sh[R_MAX * M_DIM];  // 28 KB

    const int tid  = threadIdx.x;
    const int lane = tid & 31;
    const int wid  = tid >> 5;
    const int b    = blockIdx.x;

    if (b >= 144) {
        // ---- hard: warp per column (16 cols per block) ----
        const int n = (b - 144) * 16 + wid;  // 0..63

        float v[16];
#pragma unroll
        for (int jj = 0; jj < 16; jj++)
            v[jj] = w_b[(lane + 32 * jj) * N_DIM + n];

        float t[8];
#pragma unroll
        for (int i = 0; i < 8; i++) t[i] = -3.402823466e38f;
#pragma unroll
        for (int jj = 0; jj < 16; jj++) {
            float val = v[jj];
            if (val > t[7]) {
                t[7] = val;
#pragma unroll
                for (int i = 7; i > 0; i--) {
                    if (t[i] > t[i - 1]) {
                        float tmp = t[i - 1]; t[i - 1] = t[i]; t[i] = tmp;
                    }
                }
            }
        }

        float thr = 0.0f;
#pragma unroll
        for (int it = 0; it < 8; it++) {
            float m = t[0];
#pragma unroll
            for (int o = 16; o; o >>= 1)
                m = fmaxf(m, __shfl_xor_sync(0xffffffffu, m, o));
            unsigned bal = __ballot_sync(0xffffffffu, t[0] == m);
            int src = __ffs(bal) - 1;
            if (lane == src) {
#pragma unroll
                for (int i = 0; i < 7; i++) t[i] = t[i + 1];
                t[7] = -3.402823466e38f;
            }
            thr = m;
        }

#pragma unroll
        for (int jj = 0; jj < 16; jj++) {
            float shv = v[jj] - thr + EPS_F;
            shv = fminf(fmaxf(shv, -1.0f), 1.0f);
            hard_out[(lane + 32 * jj) * N_DIM + n] = (shv + 1.0f) * 0.5f;
        }
        // fall through to 13-row gemm
    }

    if (b < NB14) {
        gemm_softmax_rows<14>(x, w_att, soft_out, x_sh, 14 * b,
                              tid, lane, wid);
    } else {
        gemm_softmax_rows<13>(x, w_att, soft_out, x_sh,
                              14 * NB14 + 13 * (b - NB14), tid, lane, wid);
    }
}

// ---------------------------------------------------------------------------
// Kernel 2: bcast (unchanged, proven ~74% DRAM).
//   mask[k,m,n] = hard[m,n]*soft[k,m];  out[k,m,n] = mask*x[k,m]
// ---------------------------------------------------------------------------
__global__ __launch_bounds__(512)
void bcast_kernel(const float* __restrict__ x,
                  const float* __restrict__ soft,
                  const float* __restrict__ hard,
                  float* __restrict__ out,
                  float* __restrict__ mask) {
    __shared__ float s_sh[M_DIM];
    __shared__ float p_sh[M_DIM];

    const int k = blockIdx.x;
    {
        int m = threadIdx.x;
        float s  = soft[(size_t)k * M_DIM + m];
        float xv = x[(size_t)k * M_DIM + m];
        s_sh[m] = s;
        p_sh[m] = s * xv;
    }
    __syncthreads();

    const float4* h4 = (const float4*)hard;
    float4* o4 = (float4*)out  + (size_t)k * (M_DIM * N_DIM / 4);
    float4* m4 = (float4*)mask + (size_t)k * (M_DIM * N_DIM / 4);

#pragma unroll 8
    for (int e = threadIdx.x; e < M_DIM * N_DIM / 4; e += 512) {
        int m = e >> 4;
        float4 h = h4[e];
        float s = s_sh[m];
        float p = p_sh[m];

        float4 mw, o;
        mw.x = h.x * s; mw.y = h.y * s; mw.z = h.z * s; mw.w = h.w * s;
        o.x  = h.x * p; o.y  = h.y * p; o.z  = h.z * p; o.w  = h.w * p;

        __stcs(&m4[e], mw);
        __stcs(&o4[e], o);
    }
}

// ---------------------------------------------------------------------------
// d_out layout (reference return order):
//   out         [K,M,N] : offset 0           (67,108,864)
//   scores_hard [M,N]   : offset 67,108,864  (32,768)
//   scores_soft [K,M]   : offset 67,141,632  (1,048,576)
//   mask_weight [K,M,N] : offset 68,190,208  (67,108,864)
// ---------------------------------------------------------------------------
extern "C" void kernel_launch(void* const* d_in, const int* in_sizes, int n_in,
                              void* d_out, int out_size) {
    const float* x     = (const float*)d_in[0];
    const float* w_att = (const float*)d_in[1];
    const float* w_b   = (const float*)d_in[2];

    float* out  = (float*)d_out;
    float* hard = out + 67108864ULL;
    float* soft = out + 67141632ULL;
    float* mask = out + 68190208ULL;

    gemm_softmax_hard_kernel<<<GRID1, 512>>>(x, w_att, w_b, soft, hard);
    bcast_kernel<<<K_DIM, 512>>>(x, soft, hard, out, mask);
}